// round 5
// baseline (speedup 1.0000x reference)
#include <cuda_runtime.h>
#include <cstdint>

#define N_NODES 50000
#define D_IN 128
#define D_OUT 64
#define N_ETYPES 3
#define E_PER_ETYPE 500000
#define P_ETYPE 0.5f
#define CAP 96   // max in-degree per (etype,node); Poisson(10) tail => never hit

// Scratch (no device mallocs allowed).
__device__ int    g_cnt[N_ETYPES * N_NODES];                    // 0.6 MB
__device__ int    g_bins[(size_t)N_ETYPES * N_NODES * CAP];     // 57.6 MB
__device__ float4 g_h[(size_t)N_NODES * (D_IN / 4)];            // 25.6 MB

__device__ __forceinline__ float tanh_fast(float x) {
    float y;
    asm("tanh.approx.f32 %0, %1;" : "=f"(y) : "f"(x));
    return y;
}

// Pass 1: bin edges by (etype, dst). One thread per edge.
__global__ void __launch_bounds__(256) bin_kernel(const int* __restrict__ edge_index)
{
    const int t = blockIdx.x * blockDim.x + threadIdx.x;
    if (t >= N_ETYPES * E_PER_ETYPE) return;
    const int e   = t / E_PER_ETYPE;
    const int idx = t - e * E_PER_ETYPE;

    const int* base = edge_index + (size_t)e * 2 * E_PER_ETYPE;
    const int src = base[idx];
    const int dst = base[E_PER_ETYPE + idx];

    const int slot = atomicAdd(&g_cnt[e * N_NODES + dst], 1);
    if (slot < CAP)
        g_bins[((size_t)e * N_NODES + dst) * CAP + slot] = src;
}

// Pass 2: pull gather-mean + tanh + residual + tanh -> g_h. One warp per node.
// No shared memory: full occupancy, L1 pipe dedicated to gather wavefronts.
__global__ void __launch_bounds__(256) gather_kernel(const float* __restrict__ feat)
{
    const int gw   = (blockIdx.x * blockDim.x + threadIdx.x) >> 5;
    const int lane = threadIdx.x & 31;
    if (gw >= N_NODES) return;
    const int n = gw;

    const float4* feat4 = reinterpret_cast<const float4*>(feat);
    const float4 f = feat4[(size_t)n * (D_IN / 4) + lane];
    float h0 = f.x, h1 = f.y, h2 = f.z, h3 = f.w;

    #pragma unroll
    for (int e = 0; e < N_ETYPES; e++) {
        const int c = g_cnt[e * N_NODES + n];
        const int* bin = g_bins + ((size_t)e * N_NODES + n) * CAP;
        float4 sa = make_float4(0.f, 0.f, 0.f, 0.f);
        float4 sb = make_float4(0.f, 0.f, 0.f, 0.f);
        int i = 0;
        for (; i + 2 <= c; i += 2) {           // 2 independent chains -> MLP
            const int2 p = *reinterpret_cast<const int2*>(bin + i);  // 8B-aligned (CAP*4 % 8 == 0)
            const float4 va = feat4[(size_t)p.x * (D_IN / 4) + lane];
            const float4 vb = feat4[(size_t)p.y * (D_IN / 4) + lane];
            sa.x += va.x; sa.y += va.y; sa.z += va.z; sa.w += va.w;
            sb.x += vb.x; sb.y += vb.y; sb.z += vb.z; sb.w += vb.w;
        }
        if (i < c) {
            const float4 va = feat4[(size_t)bin[i] * (D_IN / 4) + lane];
            sa.x += va.x; sa.y += va.y; sa.z += va.z; sa.w += va.w;
        }
        const float inv = 1.0f / fmaxf((float)c, 1.0f);
        h0 += P_ETYPE * tanh_fast((sa.x + sb.x) * inv);
        h1 += P_ETYPE * tanh_fast((sa.y + sb.y) * inv);
        h2 += P_ETYPE * tanh_fast((sa.z + sb.z) * inv);
        h3 += P_ETYPE * tanh_fast((sa.w + sb.w) * inv);
    }

    g_h[(size_t)n * (D_IN / 4) + lane] =
        make_float4(tanh_fast(h0), tanh_fast(h1), tanh_fast(h2), tanh_fast(h3));
}

// Pass 3: out = h @ W + b. Register-blocked, L1-cached, no shared memory.
// Block = 256 threads, 128 nodes. Thread (jg, oct) computes 8 nodes x 4 cols.
__global__ void __launch_bounds__(256) gemm_kernel(
    const float* __restrict__ W,
    const float* __restrict__ b,
    float* __restrict__ out)
{
    const int tid = threadIdx.x;
    const int jg  = tid & 15;          // cols 4*jg .. 4*jg+3
    const int oct = tid >> 4;          // node octet within 128-node tile
    const int n0  = blockIdx.x * 128 + oct * 8;

    const float4* W4 = reinterpret_cast<const float4*>(W);   // W4[k*16 + jg] = W[k][4jg..4jg+3]
    const float4* h4 = reinterpret_cast<const float4*>(g_h); // h4[n*32 + k4]

    // Clamped row pointers (OOB threads read node N-1, stores guarded below).
    const float4* hp[8];
    #pragma unroll
    for (int i = 0; i < 8; i++) {
        int n = n0 + i; if (n > N_NODES - 1) n = N_NODES - 1;
        hp[i] = h4 + (size_t)n * (D_IN / 4);
    }

    float acc[8][4];
    #pragma unroll
    for (int i = 0; i < 8; i++)
        #pragma unroll
        for (int j = 0; j < 4; j++) acc[i][j] = 0.f;

    for (int k4 = 0; k4 < D_IN / 4; k4++) {
        float4 wv0 = __ldg(&W4[(k4 * 4 + 0) * 16 + jg]);
        float4 wv1 = __ldg(&W4[(k4 * 4 + 1) * 16 + jg]);
        float4 wv2 = __ldg(&W4[(k4 * 4 + 2) * 16 + jg]);
        float4 wv3 = __ldg(&W4[(k4 * 4 + 3) * 16 + jg]);
        #pragma unroll
        for (int i = 0; i < 8; i++) {
            const float4 hv = __ldg(&hp[i][k4]);
            acc[i][0] = fmaf(hv.x, wv0.x, acc[i][0]); acc[i][0] = fmaf(hv.y, wv1.x, acc[i][0]);
            acc[i][0] = fmaf(hv.z, wv2.x, acc[i][0]); acc[i][0] = fmaf(hv.w, wv3.x, acc[i][0]);
            acc[i][1] = fmaf(hv.x, wv0.y, acc[i][1]); acc[i][1] = fmaf(hv.y, wv1.y, acc[i][1]);
            acc[i][1] = fmaf(hv.z, wv2.y, acc[i][1]); acc[i][1] = fmaf(hv.w, wv3.y, acc[i][1]);
            acc[i][2] = fmaf(hv.x, wv0.z, acc[i][2]); acc[i][2] = fmaf(hv.y, wv1.z, acc[i][2]);
            acc[i][2] = fmaf(hv.z, wv2.z, acc[i][2]); acc[i][2] = fmaf(hv.w, wv3.z, acc[i][2]);
            acc[i][3] = fmaf(hv.x, wv0.w, acc[i][3]); acc[i][3] = fmaf(hv.y, wv1.w, acc[i][3]);
            acc[i][3] = fmaf(hv.z, wv2.w, acc[i][3]); acc[i][3] = fmaf(hv.w, wv3.w, acc[i][3]);
        }
    }

    const float4 bias = __ldg(&reinterpret_cast<const float4*>(b)[jg]);
    float4* out4 = reinterpret_cast<float4*>(out);
    #pragma unroll
    for (int i = 0; i < 8; i++) {
        const int n = n0 + i;
        if (n < N_NODES) {
            out4[(size_t)n * (D_OUT / 4) + jg] =
                make_float4(acc[i][0] + bias.x, acc[i][1] + bias.y,
                            acc[i][2] + bias.z, acc[i][3] + bias.w);
        }
    }
}

extern "C" void kernel_launch(void* const* d_in, const int* in_sizes, int n_in,
                              void* d_out, int out_size)
{
    // Identify inputs by unique element counts (robust to metadata ordering).
    const float* feat = nullptr;
    const float* W    = nullptr;
    const float* b    = nullptr;
    const int*   ei   = nullptr;
    for (int i = 0; i < n_in; i++) {
        switch (in_sizes[i]) {
            case 6400000: feat = (const float*)d_in[i]; break;
            case 8192:    W    = (const float*)d_in[i]; break;
            case 64:      b    = (const float*)d_in[i]; break;
            case 3000000: ei   = (const int*)d_in[i];   break;
            default: break;
        }
    }
    float* out = (float*)d_out;

    void* cnt_ptr = nullptr;
    cudaGetSymbolAddress(&cnt_ptr, g_cnt);
    cudaMemsetAsync(cnt_ptr, 0, (size_t)N_ETYPES * N_NODES * sizeof(int), 0);

    const int n_edges = N_ETYPES * E_PER_ETYPE;
    bin_kernel<<<(n_edges + 255) / 256, 256>>>(ei);

    gather_kernel<<<(N_NODES + 7) / 8, 256>>>(feat);

    gemm_kernel<<<(N_NODES + 127) / 128, 256>>>(W, b, out);
}

// round 6
// speedup vs baseline: 1.1363x; 1.1363x over previous
#include <cuda_runtime.h>
#include <cuda_fp16.h>
#include <cstdint>

#define N_NODES 50000
#define D_IN 128
#define D_OUT 64
#define N_ETYPES 3
#define E_PER_ETYPE 500000
#define P_ETYPE 0.5f
#define CAP 96   // max in-degree per (etype,node); Poisson(10) tail => never hit

// Scratch (no device mallocs allowed).
__device__ int   g_cnt[N_ETYPES * N_NODES];                     // 0.6 MB
__device__ int   g_bins[(size_t)N_ETYPES * N_NODES * CAP];      // 57.6 MB
__device__ uint2 g_feat16[(size_t)N_NODES * (D_IN / 4)];        // 12.8 MB (4 halves per uint2)
__device__ uint2 g_h16[(size_t)N_NODES * (D_IN / 4)];           // 12.8 MB

__device__ __forceinline__ float tanh_fast(float x) {
    float y;
    asm("tanh.approx.f32 %0, %1;" : "=f"(y) : "f"(x));
    return y;
}

__device__ __forceinline__ uint2 pack4(float a, float b, float c, float d) {
    __half2 lo = __floats2half2_rn(a, b);
    __half2 hi = __floats2half2_rn(c, d);
    uint2 u;
    u.x = *reinterpret_cast<unsigned*>(&lo);
    u.y = *reinterpret_cast<unsigned*>(&hi);
    return u;
}

__device__ __forceinline__ float4 unpack4(uint2 u) {
    __half2 lo = *reinterpret_cast<__half2*>(&u.x);
    __half2 hi = *reinterpret_cast<__half2*>(&u.y);
    float2 a = __half22float2(lo);
    float2 c = __half22float2(hi);
    return make_float4(a.x, a.y, c.x, c.y);
}

// Convert feat fp32 -> fp16 cache (halves all gather traffic).
__global__ void __launch_bounds__(256) convert_kernel(const float* __restrict__ feat)
{
    const int i = blockIdx.x * blockDim.x + threadIdx.x;
    if (i >= N_NODES * (D_IN / 4)) return;
    const float4 v = reinterpret_cast<const float4*>(feat)[i];
    g_feat16[i] = pack4(v.x, v.y, v.z, v.w);
}

// Pass 1: bin edges by (etype, dst). 4 edges per thread -> 4 independent
// load/atomic/store chains (was issue=5.9%, pure latency bound).
__global__ void __launch_bounds__(256) bin_kernel(const int* __restrict__ edge_index)
{
    const int t = blockIdx.x * blockDim.x + threadIdx.x;
    if (t >= N_ETYPES * (E_PER_ETYPE / 4)) return;
    const int e    = t / (E_PER_ETYPE / 4);
    const int idx4 = (t - e * (E_PER_ETYPE / 4)) * 4;

    const int* base = edge_index + (size_t)e * 2 * E_PER_ETYPE;
    const int4 s = *reinterpret_cast<const int4*>(base + idx4);
    const int4 d = *reinterpret_cast<const int4*>(base + E_PER_ETYPE + idx4);

    const int s0 = atomicAdd(&g_cnt[e * N_NODES + d.x], 1);
    const int s1 = atomicAdd(&g_cnt[e * N_NODES + d.y], 1);
    const int s2 = atomicAdd(&g_cnt[e * N_NODES + d.z], 1);
    const int s3 = atomicAdd(&g_cnt[e * N_NODES + d.w], 1);

    if (s0 < CAP) g_bins[((size_t)e * N_NODES + d.x) * CAP + s0] = s.x;
    if (s1 < CAP) g_bins[((size_t)e * N_NODES + d.y) * CAP + s1] = s.y;
    if (s2 < CAP) g_bins[((size_t)e * N_NODES + d.z) * CAP + s2] = s.z;
    if (s3 < CAP) g_bins[((size_t)e * N_NODES + d.w) * CAP + s3] = s.w;
}

// Pass 2: pull gather-mean (fp16 payload, fp32 accum) + tanh + residual(fp32)
// + tanh -> g_h16. One warp per node; lane l owns columns 4l..4l+3.
__global__ void __launch_bounds__(256) gather_kernel(const float* __restrict__ feat)
{
    const int gw   = (blockIdx.x * blockDim.x + threadIdx.x) >> 5;
    const int lane = threadIdx.x & 31;
    if (gw >= N_NODES) return;
    const int n = gw;

    // Residual path stays exact fp32.
    const float4 f = reinterpret_cast<const float4*>(feat)[(size_t)n * (D_IN / 4) + lane];
    float h0 = f.x, h1 = f.y, h2 = f.z, h3 = f.w;

    #pragma unroll
    for (int e = 0; e < N_ETYPES; e++) {
        const int c = g_cnt[e * N_NODES + n];
        const int* bin = g_bins + ((size_t)e * N_NODES + n) * CAP;
        float4 sa = make_float4(0.f, 0.f, 0.f, 0.f);
        float4 sb = make_float4(0.f, 0.f, 0.f, 0.f);
        int i = 0;
        for (; i + 2 <= c; i += 2) {           // 2 independent chains -> MLP
            const int2 p = *reinterpret_cast<const int2*>(bin + i);
            const float4 va = unpack4(__ldg(&g_feat16[(size_t)p.x * (D_IN / 4) + lane]));
            const float4 vb = unpack4(__ldg(&g_feat16[(size_t)p.y * (D_IN / 4) + lane]));
            sa.x += va.x; sa.y += va.y; sa.z += va.z; sa.w += va.w;
            sb.x += vb.x; sb.y += vb.y; sb.z += vb.z; sb.w += vb.w;
        }
        if (i < c) {
            const float4 va = unpack4(__ldg(&g_feat16[(size_t)bin[i] * (D_IN / 4) + lane]));
            sa.x += va.x; sa.y += va.y; sa.z += va.z; sa.w += va.w;
        }
        const float inv = 1.0f / fmaxf((float)c, 1.0f);
        h0 += P_ETYPE * tanh_fast((sa.x + sb.x) * inv);
        h1 += P_ETYPE * tanh_fast((sa.y + sb.y) * inv);
        h2 += P_ETYPE * tanh_fast((sa.z + sb.z) * inv);
        h3 += P_ETYPE * tanh_fast((sa.w + sb.w) * inv);
    }

    g_h16[(size_t)n * (D_IN / 4) + lane] =
        pack4(tanh_fast(h0), tanh_fast(h1), tanh_fast(h2), tanh_fast(h3));
}

// Pass 3: out = h @ W + b. Register-blocked, L1-cached, no shared memory.
// Block = 256 threads, 128 nodes. Thread (jg, oct) computes 8 nodes x 4 cols.
__global__ void __launch_bounds__(256) gemm_kernel(
    const float* __restrict__ W,
    const float* __restrict__ b,
    float* __restrict__ out)
{
    const int tid = threadIdx.x;
    const int jg  = tid & 15;          // cols 4*jg .. 4*jg+3
    const int oct = tid >> 4;          // node octet within 128-node tile
    const int n0  = blockIdx.x * 128 + oct * 8;

    const float4* W4 = reinterpret_cast<const float4*>(W);   // W4[k*16 + jg] = W[k][4jg..4jg+3]

    // Clamped row pointers (OOB threads read node N-1, stores guarded below).
    const uint2* hp[8];
    #pragma unroll
    for (int i = 0; i < 8; i++) {
        int n = n0 + i; if (n > N_NODES - 1) n = N_NODES - 1;
        hp[i] = g_h16 + (size_t)n * (D_IN / 4);
    }

    float acc[8][4];
    #pragma unroll
    for (int i = 0; i < 8; i++)
        #pragma unroll
        for (int j = 0; j < 4; j++) acc[i][j] = 0.f;

    for (int k4 = 0; k4 < D_IN / 4; k4++) {
        float4 wv0 = __ldg(&W4[(k4 * 4 + 0) * 16 + jg]);
        float4 wv1 = __ldg(&W4[(k4 * 4 + 1) * 16 + jg]);
        float4 wv2 = __ldg(&W4[(k4 * 4 + 2) * 16 + jg]);
        float4 wv3 = __ldg(&W4[(k4 * 4 + 3) * 16 + jg]);
        #pragma unroll
        for (int i = 0; i < 8; i++) {
            const float4 hv = unpack4(__ldg(&hp[i][k4]));
            acc[i][0] = fmaf(hv.x, wv0.x, acc[i][0]); acc[i][0] = fmaf(hv.y, wv1.x, acc[i][0]);
            acc[i][0] = fmaf(hv.z, wv2.x, acc[i][0]); acc[i][0] = fmaf(hv.w, wv3.x, acc[i][0]);
            acc[i][1] = fmaf(hv.x, wv0.y, acc[i][1]); acc[i][1] = fmaf(hv.y, wv1.y, acc[i][1]);
            acc[i][1] = fmaf(hv.z, wv2.y, acc[i][1]); acc[i][1] = fmaf(hv.w, wv3.y, acc[i][1]);
            acc[i][2] = fmaf(hv.x, wv0.z, acc[i][2]); acc[i][2] = fmaf(hv.y, wv1.z, acc[i][2]);
            acc[i][2] = fmaf(hv.z, wv2.z, acc[i][2]); acc[i][2] = fmaf(hv.w, wv3.z, acc[i][2]);
            acc[i][3] = fmaf(hv.x, wv0.w, acc[i][3]); acc[i][3] = fmaf(hv.y, wv1.w, acc[i][3]);
            acc[i][3] = fmaf(hv.z, wv2.w, acc[i][3]); acc[i][3] = fmaf(hv.w, wv3.w, acc[i][3]);
        }
    }

    const float4 bias = __ldg(&reinterpret_cast<const float4*>(b)[jg]);
    float4* out4 = reinterpret_cast<float4*>(out);
    #pragma unroll
    for (int i = 0; i < 8; i++) {
        const int n = n0 + i;
        if (n < N_NODES) {
            out4[(size_t)n * (D_OUT / 4) + jg] =
                make_float4(acc[i][0] + bias.x, acc[i][1] + bias.y,
                            acc[i][2] + bias.z, acc[i][3] + bias.w);
        }
    }
}

extern "C" void kernel_launch(void* const* d_in, const int* in_sizes, int n_in,
                              void* d_out, int out_size)
{
    // Identify inputs by unique element counts (robust to metadata ordering).
    const float* feat = nullptr;
    const float* W    = nullptr;
    const float* b    = nullptr;
    const int*   ei   = nullptr;
    for (int i = 0; i < n_in; i++) {
        switch (in_sizes[i]) {
            case 6400000: feat = (const float*)d_in[i]; break;
            case 8192:    W    = (const float*)d_in[i]; break;
            case 64:      b    = (const float*)d_in[i]; break;
            case 3000000: ei   = (const int*)d_in[i];   break;
            default: break;
        }
    }
    float* out = (float*)d_out;

    void* cnt_ptr = nullptr;
    cudaGetSymbolAddress(&cnt_ptr, g_cnt);
    cudaMemsetAsync(cnt_ptr, 0, (size_t)N_ETYPES * N_NODES * sizeof(int), 0);

    convert_kernel<<<(N_NODES * (D_IN / 4) + 255) / 256, 256>>>(feat);

    const int groups = N_ETYPES * (E_PER_ETYPE / 4);
    bin_kernel<<<(groups + 255) / 256, 256>>>(ei);

    gather_kernel<<<(N_NODES + 7) / 8, 256>>>(feat);

    gemm_kernel<<<(N_NODES + 127) / 128, 256>>>(W, b, out);
}